// round 13
// baseline (speedup 1.0000x reference)
#include <cuda_runtime.h>
#include <cstdint>

// Graph_Learn fused, packed f32x2, 16 rows/block, software-pipelined xi.
// S[b,t,i,j] = exp(relu(sum_f a_f*|xi-xj|)) / rowsum
// (row sum == reference column sum by exact bitwise symmetry of tmpS).
// diff via fma(xj, -1x2, xi): no xj negate prologue. xi rows double-buffered.

#define Vn 256
#define Fn 64
#define Rr 16           // rows per block
#define PAD 68          // floats per smem row (17 * 16B, odd quad stride)

#define SMEM_AS   (Vn * PAD)          // a[64]
#define SMEM_FLOATS (SMEM_AS + Fn)
#define SMEM_BYTES  (SMEM_FLOATS * 4)

typedef unsigned long long u64;

__device__ __forceinline__ u64 f2fma(u64 a, u64 b, u64 c) {
    u64 d; asm("fma.rn.f32x2 %0,%1,%2,%3;" : "=l"(d) : "l"(a), "l"(b), "l"(c)); return d;
}
__device__ __forceinline__ u64 f2abs(u64 a) {
    u64 d; asm("and.b64 %0,%1,0x7FFFFFFF7FFFFFFF;" : "=l"(d) : "l"(a)); return d;
}
__device__ __forceinline__ u64 packf2(float lo, float hi) {
    u64 d; asm("mov.b64 %0,{%1,%2};" : "=l"(d) : "f"(lo), "f"(hi)); return d;
}
__device__ __forceinline__ void unpackf2(u64 v, float& lo, float& hi) {
    asm("mov.b64 {%0,%1},%2;" : "=f"(lo), "=f"(hi) : "l"(v));
}
__device__ __forceinline__ void lds_2x64(uint32_t addr, u64& p0, u64& p1) {
    asm volatile("ld.shared.v2.u64 {%0,%1},[%2];" : "=l"(p0), "=l"(p1) : "r"(addr));
}

__global__ __launch_bounds__(256, 3)
void gl_kernel(const float* __restrict__ x, const float* __restrict__ a,
               float* __restrict__ out)
{
    extern __shared__ float sm[];
    float* xs  = sm;             // [Vn][PAD]
    float* as_ = sm + SMEM_AS;   // a[64]
    __shared__ float wsum[Rr * 8];
    __shared__ float rdn[Rr];

    const int tid = threadIdx.x;
    const int i0  = blockIdx.x * Rr;
    const int bt  = blockIdx.y;
    const int j   = tid;

    // ---- stage x[bt] slice into padded smem (coalesced LDG.128) ----
    const float4* xp = (const float4*)(x + (size_t)bt * Vn * Fn);
    #pragma unroll
    for (int it = 0; it < 16; ++it) {
        int k = tid + it * 256;
        float4 v = xp[k];
        int row = k >> 4;
        int fc  = (k & 15) << 2;
        *(float4*)&xs[row * PAD + fc] = v;
    }
    if (tid < Fn) as_[tid] = a[tid];
    __syncthreads();

    const uint32_t xs_sh = (uint32_t)__cvta_generic_to_shared(xs);
    const uint32_t as_sh = (uint32_t)__cvta_generic_to_shared(as_);
    const u64 NEG1 = packf2(-1.0f, -1.0f);

    u64 acc[Rr];
    #pragma unroll
    for (int r = 0; r < Rr; ++r) acc[r] = 0ull;

    // ---- main: 8 f-chunks of 8 floats (4 packed pairs per chunk) ----
    #pragma unroll 1
    for (int c = 0; c < 8; ++c) {
        const int f0 = c << 3;
        u64 xj[4], av[4];
        {
            const uint32_t jb = xs_sh + (uint32_t)((j * PAD + f0) * 4);
            lds_2x64(jb + 0,  xj[0], xj[1]);     // raw xj, no negate prologue
            lds_2x64(jb + 16, xj[2], xj[3]);
            const uint32_t ab = as_sh + (uint32_t)(f0 * 4);
            lds_2x64(ab + 0,  av[0], av[1]);
            lds_2x64(ab + 16, av[2], av[3]);
        }

        const uint32_t base0 = xs_sh + (uint32_t)((i0 * PAD + f0) * 4);
        u64 xa[4], xb[4];
        lds_2x64(base0 + 0,  xa[0], xa[1]);      // preload row 0
        lds_2x64(base0 + 16, xa[2], xa[3]);

        #pragma unroll
        for (int r = 0; r < Rr; r += 2) {
            // prefetch row r+1 while computing row r
            const uint32_t b1 = base0 + (uint32_t)((r + 1) * PAD * 4);
            lds_2x64(b1 + 0,  xb[0], xb[1]);
            lds_2x64(b1 + 16, xb[2], xb[3]);
            {
                u64 s = acc[r];
                #pragma unroll
                for (int k = 0; k < 4; ++k) {
                    u64 d = f2abs(f2fma(xj[k], NEG1, xa[k]));  // FFMA2 + 2xLOP3
                    s = f2fma(d, av[k], s);                    // FFMA2
                }
                acc[r] = s;
            }
            // prefetch row r+2 while computing row r+1
            if (r + 2 < Rr) {
                const uint32_t b2 = base0 + (uint32_t)((r + 2) * PAD * 4);
                lds_2x64(b2 + 0,  xa[0], xa[1]);
                lds_2x64(b2 + 16, xa[2], xa[3]);
            }
            {
                u64 s = acc[r + 1];
                #pragma unroll
                for (int k = 0; k < 4; ++k) {
                    u64 d = f2abs(f2fma(xj[k], NEG1, xb[k]));
                    s = f2fma(d, av[k], s);
                }
                acc[r + 1] = s;
            }
        }
    }

    // ---- tmpS = exp(relu(lo+hi)) ----
    float f[Rr];
    #pragma unroll
    for (int r = 0; r < Rr; ++r) {
        float lo, hi;
        unpackf2(acc[r], lo, hi);
        f[r] = __expf(fmaxf(lo + hi, 0.f));
    }

    // ---- denom: row sums (== column sums by exact symmetry) ----
    const int lane = tid & 31, w = tid >> 5;
    #pragma unroll
    for (int r = 0; r < Rr; ++r) {
        float v = f[r];
        v += __shfl_xor_sync(0xffffffffu, v, 16);
        v += __shfl_xor_sync(0xffffffffu, v, 8);
        v += __shfl_xor_sync(0xffffffffu, v, 4);
        v += __shfl_xor_sync(0xffffffffu, v, 2);
        v += __shfl_xor_sync(0xffffffffu, v, 1);
        if (lane == 0) wsum[r * 8 + w] = v;
    }
    __syncthreads();
    if (tid < Rr) {
        float d = 0.f;
        #pragma unroll
        for (int q = 0; q < 8; ++q) d += wsum[tid * 8 + q];
        rdn[tid] = __fdividef(1.0f, d);
    }
    __syncthreads();

    // ---- normalize + coalesced store ----
    float* op = out + ((size_t)bt * Vn + i0) * Vn + j;
    #pragma unroll
    for (int r = 0; r < Rr; ++r)
        op[(size_t)r * Vn] = f[r] * rdn[r];
}

extern "C" void kernel_launch(void* const* d_in, const int* in_sizes, int n_in,
                              void* d_out, int out_size)
{
    const float* x = (const float*)d_in[0];
    const float* a = (const float*)d_in[1];
    if (n_in >= 2 && in_sizes[0] == Fn && in_sizes[1] > Fn) {
        x = (const float*)d_in[1];
        a = (const float*)d_in[0];
    }
    int bt = in_sizes[0] == Fn ? in_sizes[1] / (Vn * Fn) : in_sizes[0] / (Vn * Fn);

    cudaFuncSetAttribute(gl_kernel, cudaFuncAttributeMaxDynamicSharedMemorySize,
                         SMEM_BYTES);
    dim3 grid(Vn / Rr, bt);      // bt slow: co-resident blocks share the slice
    gl_kernel<<<grid, 256, SMEM_BYTES>>>(x, a, (float*)d_out);
}

// round 14
// speedup vs baseline: 1.4508x; 1.4508x over previous
#include <cuda_runtime.h>
#include <cstdint>

// Graph_Learn fused, packed f32x2. 512-thread blocks covering 16 rows
// (h-split: two 256-thread groups of 8 rows each). Combines R12's xi-broadcast
// amortization (16 rows/block) with R11's occupancy (2 blocks/SM, 32 warps).
// S[b,t,i,j] = exp(relu(sum_f a_f*|xi-xj|)) / rowsum
// (row sum == reference column sum by exact bitwise symmetry of tmpS).

#define Vn 256
#define Fn 64
#define Rr 16           // rows per block
#define HR 8            // rows per 256-thread group
#define PAD 68          // floats per smem row (17 * 16B, odd quad stride)

#define SMEM_AS   (Vn * PAD)          // a[64]
#define SMEM_FLOATS (SMEM_AS + Fn)
#define SMEM_BYTES  (SMEM_FLOATS * 4)

typedef unsigned long long u64;

__device__ __forceinline__ u64 f2add(u64 a, u64 b) {
    u64 d; asm("add.rn.f32x2 %0,%1,%2;" : "=l"(d) : "l"(a), "l"(b)); return d;
}
__device__ __forceinline__ u64 f2fma(u64 a, u64 b, u64 c) {
    u64 d; asm("fma.rn.f32x2 %0,%1,%2,%3;" : "=l"(d) : "l"(a), "l"(b), "l"(c)); return d;
}
__device__ __forceinline__ u64 f2abs(u64 a) {
    u64 d; asm("and.b64 %0,%1,0x7FFFFFFF7FFFFFFF;" : "=l"(d) : "l"(a)); return d;
}
__device__ __forceinline__ u64 packf2(float lo, float hi) {
    u64 d; asm("mov.b64 %0,{%1,%2};" : "=l"(d) : "f"(lo), "f"(hi)); return d;
}
__device__ __forceinline__ void unpackf2(u64 v, float& lo, float& hi) {
    asm("mov.b64 {%0,%1},%2;" : "=f"(lo), "=f"(hi) : "l"(v));
}
__device__ __forceinline__ void lds_2x64(uint32_t addr, u64& p0, u64& p1) {
    asm volatile("ld.shared.v2.u64 {%0,%1},[%2];" : "=l"(p0), "=l"(p1) : "r"(addr));
}

__global__ __launch_bounds__(512, 2)
void gl_kernel(const float* __restrict__ x, const float* __restrict__ a,
               float* __restrict__ out)
{
    extern __shared__ float sm[];
    float* xs  = sm;             // [Vn][PAD]
    float* as_ = sm + SMEM_AS;   // a[64]
    __shared__ float wsum[Rr * 8];
    __shared__ float rdn[Rr];

    const int tid = threadIdx.x;
    const int j   = tid & 255;               // column
    const int h   = tid >> 8;                // row-half (0/1)
    const int bt  = blockIdx.y;
    const int i0  = blockIdx.x * Rr + h * HR;  // this group's 8 rows

    // ---- stage x[bt] slice into padded smem (coalesced LDG.128) ----
    const float4* xp = (const float4*)(x + (size_t)bt * Vn * Fn);
    #pragma unroll
    for (int it = 0; it < 8; ++it) {         // 4096 float4 / 512 threads
        int k = tid + it * 512;
        float4 v = xp[k];
        int row = k >> 4;
        int fc  = (k & 15) << 2;
        *(float4*)&xs[row * PAD + fc] = v;
    }
    if (tid < Fn) as_[tid] = a[tid];
    __syncthreads();

    const uint32_t xs_sh = (uint32_t)__cvta_generic_to_shared(xs);
    const uint32_t as_sh = (uint32_t)__cvta_generic_to_shared(as_);

    u64 acc[HR];
    #pragma unroll
    for (int r = 0; r < HR; ++r) acc[r] = 0ull;

    // ---- main: 8 f-chunks of 8 floats (4 packed pairs per chunk) ----
    #pragma unroll 1
    for (int c = 0; c < 8; ++c) {
        const int f0 = c << 3;
        u64 nxj[4], av[4];
        {
            const uint32_t jb = xs_sh + (uint32_t)((j * PAD + f0) * 4);
            u64 t[4];
            lds_2x64(jb +  0, t[0], t[1]);
            lds_2x64(jb + 16, t[2], t[3]);
            #pragma unroll
            for (int q = 0; q < 4; ++q) {
                float lo, hi; unpackf2(t[q], lo, hi);
                nxj[q] = packf2(-lo, -hi);
            }
            const uint32_t ab = as_sh + (uint32_t)(f0 * 4);
            lds_2x64(ab + 0,  av[0], av[1]);
            lds_2x64(ab + 16, av[2], av[3]);
        }
        #pragma unroll
        for (int r = 0; r < HR; ++r) {
            const uint32_t base = xs_sh + (uint32_t)(((i0 + r) * PAD + f0) * 4);
            u64 xi[4];
            lds_2x64(base + 0,  xi[0], xi[1]);   // warp-uniform broadcast
            lds_2x64(base + 16, xi[2], xi[3]);
            u64 s = acc[r];
            #pragma unroll
            for (int k = 0; k < 4; ++k) {
                u64 d = f2abs(f2add(xi[k], nxj[k]));   // ADD2 + 2xLOP3
                s = f2fma(d, av[k], s);                // FFMA2
            }
            acc[r] = s;
        }
    }

    // ---- tmpS = exp(relu(lo+hi)) ----
    float f[HR];
    #pragma unroll
    for (int r = 0; r < HR; ++r) {
        float lo, hi;
        unpackf2(acc[r], lo, hi);
        f[r] = __expf(fmaxf(lo + hi, 0.f));
    }

    // ---- denom: row sums (== column sums by exact symmetry) ----
    const int lane = tid & 31;
    const int wg   = (tid >> 5) & 7;         // warp within the 256-thread group
    #pragma unroll
    for (int r = 0; r < HR; ++r) {
        float v = f[r];
        v += __shfl_xor_sync(0xffffffffu, v, 16);
        v += __shfl_xor_sync(0xffffffffu, v, 8);
        v += __shfl_xor_sync(0xffffffffu, v, 4);
        v += __shfl_xor_sync(0xffffffffu, v, 2);
        v += __shfl_xor_sync(0xffffffffu, v, 1);
        if (lane == 0) wsum[(h * HR + r) * 8 + wg] = v;
    }
    __syncthreads();
    if (tid < Rr) {
        float d = 0.f;
        #pragma unroll
        for (int q = 0; q < 8; ++q) d += wsum[tid * 8 + q];
        rdn[tid] = __fdividef(1.0f, d);
    }
    __syncthreads();

    // ---- normalize + coalesced store ----
    float* op = out + ((size_t)bt * Vn + i0) * Vn + j;
    #pragma unroll
    for (int r = 0; r < HR; ++r)
        op[(size_t)r * Vn] = f[r] * rdn[h * HR + r];
}

extern "C" void kernel_launch(void* const* d_in, const int* in_sizes, int n_in,
                              void* d_out, int out_size)
{
    const float* x = (const float*)d_in[0];
    const float* a = (const float*)d_in[1];
    if (n_in >= 2 && in_sizes[0] == Fn && in_sizes[1] > Fn) {
        x = (const float*)d_in[1];
        a = (const float*)d_in[0];
    }
    int bt = in_sizes[0] == Fn ? in_sizes[1] / (Vn * Fn) : in_sizes[0] / (Vn * Fn);

    cudaFuncSetAttribute(gl_kernel, cudaFuncAttributeMaxDynamicSharedMemorySize,
                         SMEM_BYTES);
    dim3 grid(Vn / Rr, bt);      // bt slow: co-resident blocks share the slice
    gl_kernel<<<grid, 512, SMEM_BYTES>>>(x, a, (float*)d_out);
}